// round 2
// baseline (speedup 1.0000x reference)
#include <cuda_runtime.h>
#include <math.h>

// Problem constants (fixed by the reference)
#define DM   1024
#define SQ   2048
#define BB   4
#define HH   16
#define HD   64
#define NTOK (BB * SQ)   // 8192

// ---------------------------------------------------------------------------
// Scratch (device globals; no dynamic allocation allowed)
// ---------------------------------------------------------------------------
__device__ float g_xpe[NTOK * DM];
__device__ float g_q  [NTOK * DM];
__device__ float g_k  [NTOK * DM];
__device__ float g_v  [NTOK * DM];
__device__ float g_att[NTOK * DM];

// ---------------------------------------------------------------------------
// 1) x + positional encoding  (vectorized float4)
// ---------------------------------------------------------------------------
__global__ __launch_bounds__(256) void add_pe_kernel(const float* __restrict__ x,
                                                     const float* __restrict__ pe) {
    int i = blockIdx.x * blockDim.x + threadIdx.x;  // float4 index
    float4 xv = reinterpret_cast<const float4*>(x)[i];
    int d4  = i & (DM / 4 - 1);       // float4 column in row
    int tok = i >> 8;                 // i / (DM/4)
    int s   = tok & (SQ - 1);
    float4 pv = reinterpret_cast<const float4*>(pe)[s * (DM / 4) + d4];
    xv.x += pv.x; xv.y += pv.y; xv.z += pv.z; xv.w += pv.w;
    reinterpret_cast<float4*>(g_xpe)[i] = xv;
}

// ---------------------------------------------------------------------------
// 2) SGEMM: C = A[M,K] @ W[K,N] + bias  (+ optional residual R)
//    128x128 blocktile, BK=8, 8x8 per thread, float4 global loads
// ---------------------------------------------------------------------------
template <bool ADD_RES>
__global__ __launch_bounds__(256) void sgemm_kernel(
    const float* __restrict__ A, const float* __restrict__ W,
    const float* __restrict__ bias, const float* __restrict__ R,
    float* __restrict__ C, int M, int N, int K)
{
    constexpr int BM = 128, BN = 128, BK = 8, TM = 8, TN = 8;
    __shared__ float As[BK * BM];   // transposed
    __shared__ float Bs[BK * BN];

    const int cRow = blockIdx.y, cCol = blockIdx.x;
    const int tid = threadIdx.x;
    const int threadCol = tid % (BN / TN);   // 0..15
    const int threadRow = tid / (BN / TN);   // 0..15

    A += (size_t)cRow * BM * K;
    W += cCol * BN;

    const int innerRowA = tid / 2,  innerColA = tid % 2;
    const int innerRowB = tid / 32, innerColB = tid % 32;

    float acc[TM][TN] = {};
    float regM[TM], regN[TN];

    for (int bk = 0; bk < K; bk += BK) {
        float4 ta = *reinterpret_cast<const float4*>(&A[(size_t)innerRowA * K + innerColA * 4]);
        As[(innerColA * 4 + 0) * BM + innerRowA] = ta.x;
        As[(innerColA * 4 + 1) * BM + innerRowA] = ta.y;
        As[(innerColA * 4 + 2) * BM + innerRowA] = ta.z;
        As[(innerColA * 4 + 3) * BM + innerRowA] = ta.w;
        *reinterpret_cast<float4*>(&Bs[innerRowB * BN + innerColB * 4]) =
            *reinterpret_cast<const float4*>(&W[(size_t)innerRowB * N + innerColB * 4]);
        __syncthreads();
        A += BK;
        W += (size_t)BK * N;
#pragma unroll
        for (int dot = 0; dot < BK; ++dot) {
#pragma unroll
            for (int i = 0; i < TM; ++i) regM[i] = As[dot * BM + threadRow * TM + i];
#pragma unroll
            for (int j = 0; j < TN; ++j) regN[j] = Bs[dot * BN + threadCol * TN + j];
#pragma unroll
            for (int i = 0; i < TM; ++i)
#pragma unroll
                for (int j = 0; j < TN; ++j)
                    acc[i][j] += regM[i] * regN[j];
        }
        __syncthreads();
    }

    const int rowBase = cRow * BM + threadRow * TM;
    const int colBase = cCol * BN + threadCol * TN;
#pragma unroll
    for (int i = 0; i < TM; ++i) {
        const size_t row = rowBase + i;
#pragma unroll
        for (int j = 0; j < TN; j += 4) {
            float4 bv = *reinterpret_cast<const float4*>(&bias[colBase + j]);
            float4 v;
            v.x = acc[i][j + 0] + bv.x;
            v.y = acc[i][j + 1] + bv.y;
            v.z = acc[i][j + 2] + bv.z;
            v.w = acc[i][j + 3] + bv.w;
            if (ADD_RES) {
                float4 rv = *reinterpret_cast<const float4*>(&R[row * N + colBase + j]);
                v.x += rv.x; v.y += rv.y; v.z += rv.z; v.w += rv.w;
            }
            *reinterpret_cast<float4*>(&C[row * N + colBase + j]) = v;
        }
    }
}

// ---------------------------------------------------------------------------
// 3) Flash attention: one block per (b, h, q-tile of 64).
//    256 threads = 16x16; each thread owns a 4x4 tile of scores and output.
//    Online softmax with shuffle reductions over width-16 lane groups.
// ---------------------------------------------------------------------------
__global__ __launch_bounds__(256) void flash_kernel() {
    extern __shared__ float smem[];
    float* Qs = smem;               // 64*64        (ld 64)
    float* Ks = smem + 4096;        // 64*65 padded (ld 65) — reused for P
    float* Vs = Ks + 64 * 65;       // 64*64        (ld 64)

    const int qt = blockIdx.x, h = blockIdx.y, b = blockIdx.z;
    const int tid = threadIdx.x;
    const int ty = tid >> 4, tx = tid & 15;
    const int q0 = qt * 64;
    const int r0 = ty * 4, c0 = tx * 4;

    const float* Qg = g_q + (size_t)b * SQ * DM + h * HD;
    const float* Kg = g_k + (size_t)b * SQ * DM + h * HD;
    const float* Vg = g_v + (size_t)b * SQ * DM + h * HD;

    for (int idx = tid; idx < 64 * 64; idx += 256) {
        int r = idx >> 6, c = idx & 63;
        Qs[idx] = Qg[(size_t)(q0 + r) * DM + c];
    }

    float o[4][4] = {};
    float m_r[4], l_r[4];
#pragma unroll
    for (int i = 0; i < 4; ++i) { m_r[i] = -1e30f; l_r[i] = 0.f; }

    const float scale = 0.125f;  // 1/sqrt(64)

    for (int kt = 0; kt < SQ / 64; ++kt) {
        const int k0 = kt * 64;
        __syncthreads();  // previous tile's P/V reads done (also publishes Q on iter 0)
        for (int idx = tid; idx < 64 * 64; idx += 256) {
            int r = idx >> 6, c = idx & 63;
            float kval = Kg[(size_t)(k0 + r) * DM + c];
            float vval = Vg[(size_t)(k0 + r) * DM + c];
            Ks[r * 65 + c] = kval;
            Vs[idx] = vval;
        }
        __syncthreads();

        // scores S = Q K^T  (4x4 per thread)
        float sc[4][4] = {};
#pragma unroll 4
        for (int k = 0; k < 64; ++k) {
            float qf[4], kf[4];
#pragma unroll
            for (int i = 0; i < 4; ++i) qf[i] = Qs[(r0 + i) * 64 + k];
#pragma unroll
            for (int j = 0; j < 4; ++j) kf[j] = Ks[(c0 + j) * 65 + k];
#pragma unroll
            for (int i = 0; i < 4; ++i)
#pragma unroll
                for (int j = 0; j < 4; ++j)
                    sc[i][j] += qf[i] * kf[j];
        }

        // online softmax (per row, reduced over the 16 threads sharing the row)
        float sclf[4];
#pragma unroll
        for (int i = 0; i < 4; ++i) {
#pragma unroll
            for (int j = 0; j < 4; ++j) sc[i][j] *= scale;
            float pm = fmaxf(fmaxf(sc[i][0], sc[i][1]), fmaxf(sc[i][2], sc[i][3]));
#pragma unroll
            for (int off = 8; off; off >>= 1)
                pm = fmaxf(pm, __shfl_xor_sync(0xffffffffu, pm, off, 16));
            float mnew = fmaxf(m_r[i], pm);
            sclf[i] = __expf(m_r[i] - mnew);
            m_r[i] = mnew;
            float ps = 0.f;
#pragma unroll
            for (int j = 0; j < 4; ++j) {
                float p = __expf(sc[i][j] - mnew);
                sc[i][j] = p;
                ps += p;
            }
#pragma unroll
            for (int off = 8; off; off >>= 1)
                ps += __shfl_xor_sync(0xffffffffu, ps, off, 16);
            l_r[i] = l_r[i] * sclf[i] + ps;
        }

        __syncthreads();  // everyone done reading Ks — safe to overwrite with P
#pragma unroll
        for (int i = 0; i < 4; ++i)
#pragma unroll
            for (int j = 0; j < 4; ++j)
                Ks[(r0 + i) * 65 + (c0 + j)] = sc[i][j];
#pragma unroll
        for (int i = 0; i < 4; ++i)
#pragma unroll
            for (int j = 0; j < 4; ++j)
                o[i][j] *= sclf[i];
        __syncthreads();  // P visible

        // O += P @ V
#pragma unroll 2
        for (int c = 0; c < 64; ++c) {
            float pf[4];
#pragma unroll
            for (int i = 0; i < 4; ++i) pf[i] = Ks[(r0 + i) * 65 + c];
            float4 vv = *reinterpret_cast<const float4*>(&Vs[c * 64 + c0]);
#pragma unroll
            for (int i = 0; i < 4; ++i) {
                o[i][0] += pf[i] * vv.x;
                o[i][1] += pf[i] * vv.y;
                o[i][2] += pf[i] * vv.z;
                o[i][3] += pf[i] * vv.w;
            }
        }
    }

    float* Og = g_att + (size_t)b * SQ * DM + h * HD;
#pragma unroll
    for (int i = 0; i < 4; ++i) {
        float inv = 1.f / l_r[i];
        float4 v = make_float4(o[i][0] * inv, o[i][1] * inv, o[i][2] * inv, o[i][3] * inv);
        *reinterpret_cast<float4*>(&Og[(size_t)(q0 + r0 + i) * DM + c0]) = v;
    }
}

// ---------------------------------------------------------------------------
// 4) In-place LayerNorm over last dim (1024), one block per row
// ---------------------------------------------------------------------------
__global__ __launch_bounds__(256) void layernorm_kernel(float* __restrict__ out,
                                                        const float* __restrict__ gamma,
                                                        const float* __restrict__ beta) {
    const int row = blockIdx.x, tid = threadIdx.x;
    float4* rowp = reinterpret_cast<float4*>(out) + (size_t)row * 256;
    float4 v = rowp[tid];
    float sum = v.x + v.y + v.z + v.w;
    float sq  = v.x * v.x + v.y * v.y + v.z * v.z + v.w * v.w;
#pragma unroll
    for (int off = 16; off; off >>= 1) {
        sum += __shfl_xor_sync(0xffffffffu, sum, off);
        sq  += __shfl_xor_sync(0xffffffffu, sq, off);
    }
    __shared__ float s1[8], s2[8];
    __shared__ float s_mu, s_inv;
    const int wid = tid >> 5, lane = tid & 31;
    if (lane == 0) { s1[wid] = sum; s2[wid] = sq; }
    __syncthreads();
    if (tid == 0) {
        float ts = 0.f, tq = 0.f;
#pragma unroll
        for (int w = 0; w < 8; ++w) { ts += s1[w]; tq += s2[w]; }
        float mu  = ts * (1.f / 1024.f);
        float var = tq * (1.f / 1024.f) - mu * mu;
        s_mu = mu;
        s_inv = rsqrtf(var + 1e-5f);
    }
    __syncthreads();
    const float mu = s_mu, inv = s_inv;
    float4 g  = reinterpret_cast<const float4*>(gamma)[tid];
    float4 be = reinterpret_cast<const float4*>(beta)[tid];
    v.x = (v.x - mu) * inv * g.x + be.x;
    v.y = (v.y - mu) * inv * g.y + be.y;
    v.z = (v.z - mu) * inv * g.z + be.z;
    v.w = (v.w - mu) * inv * g.w + be.w;
    rowp[tid] = v;
}

// ---------------------------------------------------------------------------
// launch
// ---------------------------------------------------------------------------
extern "C" void kernel_launch(void* const* d_in, const int* in_sizes, int n_in,
                              void* d_out, int out_size) {
    const float* x     = (const float*)d_in[0];
    const float* wq    = (const float*)d_in[1];
    const float* bq    = (const float*)d_in[2];
    const float* wk    = (const float*)d_in[3];
    const float* bk    = (const float*)d_in[4];
    const float* wv    = (const float*)d_in[5];
    const float* bv    = (const float*)d_in[6];
    const float* wo    = (const float*)d_in[7];
    const float* bo    = (const float*)d_in[8];
    const float* gamma = (const float*)d_in[9];
    const float* beta  = (const float*)d_in[10];
    const float* pe    = (const float*)d_in[11];
    float* out = (float*)d_out;

    float *p_xpe, *p_q, *p_k, *p_v, *p_att;
    cudaGetSymbolAddress((void**)&p_xpe, g_xpe);
    cudaGetSymbolAddress((void**)&p_q,   g_q);
    cudaGetSymbolAddress((void**)&p_k,   g_k);
    cudaGetSymbolAddress((void**)&p_v,   g_v);
    cudaGetSymbolAddress((void**)&p_att, g_att);

    // 1) x + pe
    add_pe_kernel<<<NTOK * DM / 4 / 256, 256>>>(x, pe);

    // 2) Q/K/V projections
    dim3 gg(DM / 128, NTOK / 128);
    sgemm_kernel<false><<<gg, 256>>>(p_xpe, wq, bq, nullptr, p_q, NTOK, DM, DM);
    sgemm_kernel<false><<<gg, 256>>>(p_xpe, wk, bk, nullptr, p_k, NTOK, DM, DM);
    sgemm_kernel<false><<<gg, 256>>>(p_xpe, wv, bv, nullptr, p_v, NTOK, DM, DM);

    // 3) attention
    const int smem_bytes = (64 * 64 + 64 * 65 + 64 * 64) * 4;  // 49408
    cudaFuncSetAttribute(flash_kernel, cudaFuncAttributeMaxDynamicSharedMemorySize, smem_bytes);
    flash_kernel<<<dim3(SQ / 64, HH, BB), 256, smem_bytes>>>();

    // 4) output projection + residual, written to d_out
    sgemm_kernel<true><<<gg, 256>>>(p_att, wo, bo, p_xpe, out, NTOK, DM, DM);

    // 5) in-place layernorm
    layernorm_kernel<<<NTOK, 256>>>(out, gamma, beta);
}

// round 4
// speedup vs baseline: 7.5082x; 7.5082x over previous
#include <cuda_runtime.h>
#include <cuda_fp16.h>
#include <math.h>
#include <stdint.h>

// Problem constants (fixed by the reference)
#define DM   1024
#define SQ   2048
#define BB   4
#define HH   16
#define HD   64
#define NTOK (BB * SQ)   // 8192

// ---------------------------------------------------------------------------
// Scratch (device globals; no dynamic allocation allowed)
// ---------------------------------------------------------------------------
__device__ float  g_xpe[NTOK * DM];      // x + pe, fp32 (residual)
__device__ __half g_xh [NTOK * DM];      // x + pe, fp16 (GEMM A)
__device__ __half g_wTh[4 * DM * DM];    // transposed fp16 weights [N][K]
__device__ __half g_qh [NTOK * DM];
__device__ __half g_kh [NTOK * DM];
__device__ __half g_vh [NTOK * DM];
__device__ __half g_vt [NTOK * DM];      // V transposed: [b][h][d][s]
__device__ __half g_ah [NTOK * DM];      // attention out, fp16

// ---------------------------------------------------------------------------
// helpers
// ---------------------------------------------------------------------------
__device__ __forceinline__ uint32_t smem_u32(const void* p) {
    uint32_t a;
    asm("{ .reg .u64 t; cvta.to.shared.u64 t, %1; cvt.u32.u64 %0, t; }" : "=r"(a) : "l"(p));
    return a;
}

#define CP_ASYNC16(saddr, gptr) \
    asm volatile("cp.async.cg.shared.global [%0], [%1], 16;" :: "r"(saddr), "l"(gptr))
#define CP_COMMIT() asm volatile("cp.async.commit_group;" ::: "memory")
#define CP_WAIT1()  asm volatile("cp.async.wait_group 1;" ::: "memory")
#define CP_WAIT0()  asm volatile("cp.async.wait_group 0;" ::: "memory")

// D(f32x4) += A(f16 m16k16) * B(f16 k16n8)
__device__ __forceinline__ void mma_f16(float& d0, float& d1, float& d2, float& d3,
    uint32_t a0, uint32_t a1, uint32_t a2, uint32_t a3, uint32_t b0, uint32_t b1)
{
    asm volatile("mma.sync.aligned.m16n8k16.row.col.f32.f16.f16.f32 "
        "{%0,%1,%2,%3}, {%4,%5,%6,%7}, {%8,%9}, {%0,%1,%2,%3};"
        : "+f"(d0), "+f"(d1), "+f"(d2), "+f"(d3)
        : "r"(a0), "r"(a1), "r"(a2), "r"(a3), "r"(b0), "r"(b1));
}

// ---------------------------------------------------------------------------
// 1) x + pe -> fp32 copy (residual) + fp16 copy (GEMM A)
// ---------------------------------------------------------------------------
__global__ __launch_bounds__(256) void add_pe_kernel(const float* __restrict__ x,
                                                     const float* __restrict__ pe) {
    int i = blockIdx.x * blockDim.x + threadIdx.x;  // float4 index
    float4 xv = reinterpret_cast<const float4*>(x)[i];
    int d4  = i & (DM / 4 - 1);
    int tok = i >> 8;
    int s   = tok & (SQ - 1);
    float4 pv = reinterpret_cast<const float4*>(pe)[s * (DM / 4) + d4];
    xv.x += pv.x; xv.y += pv.y; xv.z += pv.z; xv.w += pv.w;
    reinterpret_cast<float4*>(g_xpe)[i] = xv;
    __half2 h0 = __floats2half2_rn(xv.x, xv.y);
    __half2 h1 = __floats2half2_rn(xv.z, xv.w);
    reinterpret_cast<__half2*>(g_xh)[i * 2 + 0] = h0;
    reinterpret_cast<__half2*>(g_xh)[i * 2 + 1] = h1;
}

// ---------------------------------------------------------------------------
// 1b) weight transpose + fp16:  WT[n][k] = half(W[k][n])
// ---------------------------------------------------------------------------
__global__ __launch_bounds__(256) void transpose_w_kernel(const float* __restrict__ W,
                                                          __half* __restrict__ WT) {
    __shared__ float t[32][33];
    int tx = threadIdx.x, ty = threadIdx.y;       // 32 x 8
    int x = blockIdx.x * 32 + tx;                 // n
    int y = blockIdx.y * 32 + ty;                 // k
#pragma unroll
    for (int i = 0; i < 32; i += 8)
        t[ty + i][tx] = W[(size_t)(y + i) * DM + x];
    __syncthreads();
    int x2 = blockIdx.y * 32 + tx;                // k
    int y2 = blockIdx.x * 32 + ty;                // n
#pragma unroll
    for (int i = 0; i < 32; i += 8)
        WT[(size_t)(y2 + i) * DM + x2] = __float2half(t[tx][ty + i]);
}

// ---------------------------------------------------------------------------
// 1c) V transpose: g_vh [tok][DM] -> g_vt [b][h][d][s]  (half)
// ---------------------------------------------------------------------------
__global__ __launch_bounds__(256) void v_transpose_kernel() {
    __shared__ __half t[32][33];
    int tx = threadIdx.x, ty = threadIdx.y;       // 32 x 8
    int z = blockIdx.z;                           // b*16 + h
    int b = z >> 4, h = z & 15;
    int s0 = blockIdx.x * 32, d0 = blockIdx.y * 32;
#pragma unroll
    for (int i = 0; i < 32; i += 8)
        t[ty + i][tx] = g_vh[((size_t)(b * SQ + s0 + ty + i)) * DM + h * HD + d0 + tx];
    __syncthreads();
#pragma unroll
    for (int i = 0; i < 32; i += 8)
        g_vt[((size_t)z * HD + d0 + ty + i) * SQ + s0 + tx] = t[tx][ty + i];
}

// ---------------------------------------------------------------------------
// 2) fp16 tensor-core GEMM: C[M,1024] = A @ WT^T + bias (+ residual)
//    128x128 CTA tile, 8 warps (2x4) of 64x32, BK=64, cp.async double buffer.
//    A [M][K] half, WT [N][K] half. HALF_OUT: write half C; else fp32 + R.
// ---------------------------------------------------------------------------
#define HG_STRIDE 72                      // halfs per smem row (36 words)
#define HG_BUF    (128 * HG_STRIDE)      // halfs per matrix buffer

template <bool HALF_OUT>
__global__ __launch_bounds__(256) void hgemm_kernel(
    const __half* __restrict__ A, const __half* __restrict__ BT,
    const float* __restrict__ bias, const float* __restrict__ R,
    void* __restrict__ Cout)
{
    extern __shared__ __half hsm[];
    __half* As = hsm;                     // [2][128][72]
    __half* Bs = hsm + 2 * HG_BUF;        // [2][128][72]

    const int tid = threadIdx.x;
    const int wid = tid >> 5, lane = tid & 31;
    const int r = lane >> 2, cq = lane & 3;
    const int wm = (wid >> 2) * 64;       // warp m offset
    const int wn = (wid & 3) * 32;        // warp n offset
    const int m0 = blockIdx.y * 128, n0 = blockIdx.x * 128;

    // cp.async geometry: tile 128 rows x 64 halfs = 8 chunks/row; 1024 chunks/256 = 4 each
    const __half* ag[4]; const __half* bg[4]; uint32_t so[4];
#pragma unroll
    for (int i = 0; i < 4; ++i) {
        int idx = i * 256 + tid;
        int row = idx >> 3, c8 = idx & 7;
        ag[i] = A  + (size_t)(m0 + row) * DM + c8 * 8;
        bg[i] = BT + (size_t)(n0 + row) * DM + c8 * 8;
        so[i] = (uint32_t)(row * HG_STRIDE + c8 * 8) * 2;   // bytes
    }
    const uint32_t As_u = smem_u32(As), Bs_u = smem_u32(Bs);

    float acc[16][4] = {};   // [mt*4+nt]

    // prologue: buffer 0, k=0
#pragma unroll
    for (int i = 0; i < 4; ++i) {
        CP_ASYNC16(As_u + so[i], ag[i]);
        CP_ASYNC16(Bs_u + so[i], bg[i]);
    }
    CP_COMMIT();

    for (int s = 0; s < 16; ++s) {        // K = 1024, BK = 64
        const int buf = s & 1;
        if (s + 1 < 16) {
            const int ob = buf ^ 1;
            const int koff = (s + 1) * 64;
#pragma unroll
            for (int i = 0; i < 4; ++i) {
                CP_ASYNC16(As_u + (uint32_t)(ob * HG_BUF * 2) + so[i], ag[i] + koff);
                CP_ASYNC16(Bs_u + (uint32_t)(ob * HG_BUF * 2) + so[i], bg[i] + koff);
            }
            CP_COMMIT();
            CP_WAIT1();
        } else {
            CP_WAIT0();
        }
        __syncthreads();

        const uint32_t* Aw = reinterpret_cast<const uint32_t*>(As + buf * HG_BUF);
        const uint32_t* Bw = reinterpret_cast<const uint32_t*>(Bs + buf * HG_BUF);

#pragma unroll
        for (int kt = 0; kt < 4; ++kt) {          // 4 x k16
            uint32_t af[4][4], bf[4][2];
#pragma unroll
            for (int mt = 0; mt < 4; ++mt) {
                int w = (wm + mt * 16 + r) * 36 + kt * 8 + cq;
                af[mt][0] = Aw[w];
                af[mt][1] = Aw[w + 8 * 36];
                af[mt][2] = Aw[w + 4];
                af[mt][3] = Aw[w + 8 * 36 + 4];
            }
#pragma unroll
            for (int nt = 0; nt < 4; ++nt) {
                int w = (wn + nt * 8 + r) * 36 + kt * 8 + cq;
                bf[nt][0] = Bw[w];
                bf[nt][1] = Bw[w + 4];
            }
#pragma unroll
            for (int mt = 0; mt < 4; ++mt)
#pragma unroll
                for (int nt = 0; nt < 4; ++nt)
                    mma_f16(acc[mt * 4 + nt][0], acc[mt * 4 + nt][1],
                            acc[mt * 4 + nt][2], acc[mt * 4 + nt][3],
                            af[mt][0], af[mt][1], af[mt][2], af[mt][3],
                            bf[nt][0], bf[nt][1]);
        }
        __syncthreads();
    }

    // epilogue
#pragma unroll
    for (int mt = 0; mt < 4; ++mt) {
        const int row0 = m0 + wm + mt * 16 + r;
#pragma unroll
        for (int nt = 0; nt < 4; ++nt) {
            const int col = n0 + wn + nt * 8 + cq * 2;
            float2 bv = *reinterpret_cast<const float2*>(&bias[col]);
            float* a4 = acc[mt * 4 + nt];
            float v00 = a4[0] + bv.x, v01 = a4[1] + bv.y;
            float v10 = a4[2] + bv.x, v11 = a4[3] + bv.y;
            if (HALF_OUT) {
                __half* C = (__half*)Cout;
                *reinterpret_cast<__half2*>(&C[(size_t)row0 * DM + col]) =
                    __floats2half2_rn(v00, v01);
                *reinterpret_cast<__half2*>(&C[(size_t)(row0 + 8) * DM + col]) =
                    __floats2half2_rn(v10, v11);
            } else {
                float* C = (float*)Cout;
                float2 r0v = *reinterpret_cast<const float2*>(&R[(size_t)row0 * DM + col]);
                float2 r1v = *reinterpret_cast<const float2*>(&R[(size_t)(row0 + 8) * DM + col]);
                *reinterpret_cast<float2*>(&C[(size_t)row0 * DM + col]) =
                    make_float2(v00 + r0v.x, v01 + r0v.y);
                *reinterpret_cast<float2*>(&C[(size_t)(row0 + 8) * DM + col]) =
                    make_float2(v10 + r1v.x, v11 + r1v.y);
            }
        }
    }
}

// ---------------------------------------------------------------------------
// 3) Flash attention, fp16 mma + h2exp2 softmax.
//    Block: 256 thr (8 warps x 16 q-rows = 128 q-rows), K-tiles of 64.
//    l (softmax denom) accumulated via ones-row appended to V tile (tile dt=8).
// ---------------------------------------------------------------------------
#define FQ_H   (128 * 72)   // Q halfs
#define FK_H   (64 * 72)    // K halfs per buffer
#define FV_H   (72 * 72)    // Vt halfs per buffer (72 d-rows: 64 data + ones + 7 zero)
#define F_SMEM ((FQ_H + 2 * FK_H + 2 * FV_H) * 2)   // bytes = 57600

__global__ __launch_bounds__(256) void flash_kernel() {
    extern __shared__ __half hsm[];
    __half* Qs  = hsm;                       // [128][72]
    __half* Ksm = hsm + FQ_H;                // [2][64][72]
    __half* Vts = hsm + FQ_H + 2 * FK_H;     // [2][72][72]

    const int qt = blockIdx.x, h = blockIdx.y, b = blockIdx.z;
    const int tid = threadIdx.x, wid = tid >> 5, lane = tid & 31;
    const int r = lane >> 2, cq = lane & 3;
    const int q0 = qt * 128;
    const int bh = b * HH + h;

    const __half* Qg = g_qh + (size_t)b * SQ * DM + h * HD;
    const __half* Kg = g_kh + (size_t)b * SQ * DM + h * HD;
    const __half* Vg = g_vt + (size_t)bh * HD * SQ;      // [d][s]

    // load Q tile [128][64] and init Vt pad rows (64..71): ones row 64, zeros 65..71
    for (int idx = tid; idx < 128 * 8; idx += 256) {     // 16B chunks
        int row = idx >> 3, c8 = idx & 7;
        *reinterpret_cast<uint4*>(&Qs[row * 72 + c8 * 8]) =
            *reinterpret_cast<const uint4*>(&Qg[(size_t)(q0 + row) * DM + c8 * 8]);
    }
    for (int i = tid; i < 2 * 8 * 72; i += 256) {
        int buf = i / (8 * 72), rem = i % (8 * 72);
        int dr = 64 + rem / 72, c = rem % 72;
        Vts[buf * FV_H + dr * 72 + c] = (dr == 64) ? __float2half(1.f) : __float2half(0.f);
    }

    // cp.async geometry for K / Vt tiles: 64 rows x 64 halfs = 512 chunks / 256 = 2 each
    const __half* kg[2]; const __half* vg[2]; uint32_t kvo[2];
#pragma unroll
    for (int i = 0; i < 2; ++i) {
        int idx = i * 256 + tid;
        int row = idx >> 3, c8 = idx & 7;
        kg[i] = Kg + (size_t)row * DM + c8 * 8;   // K rows: seq, advance by t*64*DM
        vg[i] = Vg + (size_t)row * SQ + c8 * 8;   // Vt rows: d, cols advance by t*64
        kvo[i] = (uint32_t)(row * 72 + c8 * 8) * 2;
    }
    const uint32_t Ks_u = smem_u32(Ksm), Vt_u = smem_u32(Vts);

    __syncthreads();   // Q + pad rows visible

    // preload Q fragments (4 k16-tiles)
    uint32_t qa[4][4];
    {
        const uint32_t* Qw = reinterpret_cast<const uint32_t*>(Qs);
        int row = wid * 16 + r;
#pragma unroll
        for (int kt = 0; kt < 4; ++kt) {
            int w = row * 36 + kt * 8 + cq;
            qa[kt][0] = Qw[w];
            qa[kt][1] = Qw[w + 8 * 36];
            qa[kt][2] = Qw[w + 4];
            qa[kt][3] = Qw[w + 8 * 36 + 4];
        }
    }

    // prologue: tile 0 into buffer 0
#pragma unroll
    for (int i = 0; i < 2; ++i) {
        CP_ASYNC16(Ks_u + kvo[i], kg[i]);
        CP_ASYNC16(Vt_u + kvo[i], vg[i]);
    }
    CP_COMMIT();

    float o[9][4] = {};                   // 8 d-tiles + l-tile
    float m0s = -1e30f, m1s = -1e30f;     // running max (log2-scaled domain)
    const float LC = 0.18033688f;         // 0.125 * log2(e)

    for (int t = 0; t < SQ / 64; ++t) {
        const int buf = t & 1;
        if (t + 1 < SQ / 64) {
            const int ob = buf ^ 1;
#pragma unroll
            for (int i = 0; i < 2; ++i) {
                CP_ASYNC16(Ks_u + (uint32_t)(ob * FK_H * 2) + kvo[i],
                           kg[i] + (size_t)(t + 1) * 64 * DM);
                CP_ASYNC16(Vt_u + (uint32_t)(ob * FV_H * 2) + kvo[i],
                           vg[i] + (t + 1) * 64);
            }
            CP_COMMIT();
            CP_WAIT1();
        } else {
            CP_WAIT0();
        }
        __syncthreads();

        const uint32_t* Kw = reinterpret_cast<const uint32_t*>(Ksm + buf * FK_H);
        const uint32_t* Vw = reinterpret_cast<const uint32_t*>(Vts + buf * FV_H);

        // S = Q K^T : 8 n-tiles x 4 k16
        float s[8][4] = {};
#pragma unroll
        for (int nt = 0; nt < 8; ++nt) {
#pragma unroll
            for (int kt = 0; kt < 4; ++kt) {
                int w = (nt * 8 + r) * 36 + kt * 8 + cq;
                mma_f16(s[nt][0], s[nt][1], s[nt][2], s[nt][3],
                        qa[kt][0], qa[kt][1], qa[kt][2], qa[kt][3],
                        Kw[w], Kw[w + 4]);
            }
        }

        // online softmax (rows r and r+8; reduce over 4 threads sharing each row)
        float rm0 = -1e30f, rm1 = -1e30f;
#pragma unroll
        for (int nt = 0; nt < 8; ++nt) {
            rm0 = fmaxf(rm0, fmaxf(s[nt][0], s[nt][1]));
            rm1 = fmaxf(rm1, fmaxf(s[nt][2], s[nt][3]));
        }
        rm0 = fmaxf(rm0, __shfl_xor_sync(0xffffffffu, rm0, 1));
        rm0 = fmaxf(rm0, __shfl_xor_sync(0xffffffffu, rm0, 2));
        rm1 = fmaxf(rm1, __shfl_xor_sync(0xffffffffu, rm1, 1));
        rm1 = fmaxf(rm1, __shfl_xor_sync(0xffffffffu, rm1, 2));
        const float mn0 = fmaxf(m0s, rm0 * LC);
        const float mn1 = fmaxf(m1s, rm1 * LC);
        const float al0 = exp2f(m0s - mn0);
        const float al1 = exp2f(m1s - mn1);
        m0s = mn0; m1s = mn1;

        // P = exp2(S*LC - m), half2 pairs == fp16 A-fragment registers
        uint32_t ph0[8], ph1[8];
#pragma unroll
        for (int nt = 0; nt < 8; ++nt) {
            __half2 e0 = h2exp2(__floats2half2_rn(fmaf(s[nt][0], LC, -mn0),
                                                  fmaf(s[nt][1], LC, -mn0)));
            __half2 e1 = h2exp2(__floats2half2_rn(fmaf(s[nt][2], LC, -mn1),
                                                  fmaf(s[nt][3], LC, -mn1)));
            ph0[nt] = *reinterpret_cast<uint32_t*>(&e0);
            ph1[nt] = *reinterpret_cast<uint32_t*>(&e1);
        }

        // rescale O (and the l-tile) by alpha
#pragma unroll
        for (int dt = 0; dt < 9; ++dt) {
            o[dt][0] *= al0; o[dt][1] *= al0;
            o[dt][2] *= al1; o[dt][3] *= al1;
        }

        // O += P @ V  (dt = 8 accumulates row sums via ones-row)
#pragma unroll
        for (int jt = 0; jt < 4; ++jt) {
            uint32_t a0 = ph0[2 * jt], a1 = ph1[2 * jt];
            uint32_t a2 = ph0[2 * jt + 1], a3 = ph1[2 * jt + 1];
#pragma unroll
            for (int dt = 0; dt < 9; ++dt) {
                int w = (dt * 8 + r) * 36 + jt * 8 + cq;
                mma_f16(o[dt][0], o[dt][1], o[dt][2], o[dt][3],
                        a0, a1, a2, a3, Vw[w], Vw[w + 4]);
            }
        }
        __syncthreads();
    }

    // l lives in o[8][0]/o[8][2] of the cq==0 thread of each row group
    const float l0 = __shfl_sync(0xffffffffu, o[8][0], lane & ~3);
    const float l1 = __shfl_sync(0xffffffffu, o[8][2], lane & ~3);
    const float inv0 = 1.f / l0, inv1 = 1.f / l1;

    __half* Og = g_ah + (size_t)b * SQ * DM + h * HD;
    const int row0 = q0 + wid * 16 + r;
#pragma unroll
    for (int dt = 0; dt < 8; ++dt) {
        const int col = dt * 8 + cq * 2;
        *reinterpret_cast<__half2*>(&Og[(size_t)row0 * DM + col]) =
            __floats2half2_rn(o[dt][0] * inv0, o[dt][1] * inv0);
        *reinterpret_cast<__half2*>(&Og[(size_t)(row0 + 8) * DM + col]) =
            __floats2half2_rn(o[dt][2] * inv1, o[dt][3] * inv1);
    }
}

// ---------------------------------------------------------------------------
// 4) In-place LayerNorm over last dim (1024), one block per row
// ---------------------------------------------------------------------------
__global__ __launch_bounds__(256) void layernorm_kernel(float* __restrict__ out,
                                                        const float* __restrict__ gamma,
                                                        const float* __restrict__ beta) {
    const int row = blockIdx.x, tid = threadIdx.x;
    float4* rowp = reinterpret_cast<float4*>(out) + (size_t)row * 256;
    float4 v = rowp[tid];
    float sum = v.x + v.y + v.z + v.w;
    float sq  = v.x * v.x + v.y * v.y + v.z * v.z + v.w * v.w;
#pragma unroll
    for (int off = 16; off; off >>= 1) {
        sum += __shfl_xor_sync(0xffffffffu, sum, off);
        sq  += __shfl_xor_sync(0xffffffffu, sq, off);
    }
    __shared__ float s1[8], s2[8];
    __shared__ float s_mu, s_inv;
    const int wid = tid >> 5, lane = tid & 31;
    if (lane == 0) { s1[wid] = sum; s2[wid] = sq; }
    __syncthreads();
    if (tid == 0) {
        float ts = 0.f, tq = 0.f;
#pragma unroll
        for (int w = 0; w < 8; ++w) { ts += s1[w]; tq += s2[w]; }
        float mu  = ts * (1.f / 1024.f);
        float var = tq * (1.f / 1024.f) - mu * mu;
        s_mu = mu;
        s_inv = rsqrtf(var + 1e-5f);
    }
    __syncthreads();
    const float mu = s_mu, inv = s_inv;
    float4 g  = reinterpret_cast<const float4*>(gamma)[tid];
    float4 be = reinterpret_cast<const float4*>(beta)[tid];
    v.x = (v.x - mu) * inv * g.x + be.x;
    v.y = (v.y - mu) * inv * g.y + be.y;
    v.z = (v.z - mu) * inv * g.z + be.z;
    v.w = (v.w - mu) * inv * g.w + be.w;
    rowp[tid] = v;
}

// ---------------------------------------------------------------------------
// launch
// ---------------------------------------------------------------------------
extern "C" void kernel_launch(void* const* d_in, const int* in_sizes, int n_in,
                              void* d_out, int out_size) {
    const float* x     = (const float*)d_in[0];
    const float* wq    = (const float*)d_in[1];
    const float* bq    = (const float*)d_in[2];
    const float* wk    = (const float*)d_in[3];
    const float* bk    = (const float*)d_in[4];
    const float* wv    = (const float*)d_in[5];
    const float* bv    = (const float*)d_in[6];
    const float* wo    = (const float*)d_in[7];
    const float* bo    = (const float*)d_in[8];
    const float* gamma = (const float*)d_in[9];
    const float* beta  = (const float*)d_in[10];
    const float* pe    = (const float*)d_in[11];
    float* out = (float*)d_out;

    float *p_xpe;
    __half *p_xh, *p_wT, *p_qh, *p_kh, *p_vh, *p_ah;
    cudaGetSymbolAddress((void**)&p_xpe, g_xpe);
    cudaGetSymbolAddress((void**)&p_xh,  g_xh);
    cudaGetSymbolAddress((void**)&p_wT,  g_wTh);
    cudaGetSymbolAddress((void**)&p_qh,  g_qh);
    cudaGetSymbolAddress((void**)&p_kh,  g_kh);
    cudaGetSymbolAddress((void**)&p_vh,  g_vh);
    cudaGetSymbolAddress((void**)&p_ah,  g_ah);

    // 1) x + pe
    add_pe_kernel<<<NTOK * DM / 4 / 256, 256>>>(x, pe);

    // 1b) transpose + halve weights
    dim3 tb(32, 8), tg(DM / 32, DM / 32);
    transpose_w_kernel<<<tg, tb>>>(wq, p_wT + 0 * DM * DM);
    transpose_w_kernel<<<tg, tb>>>(wk, p_wT + 1 * DM * DM);
    transpose_w_kernel<<<tg, tb>>>(wv, p_wT + 2 * DM * DM);
    transpose_w_kernel<<<tg, tb>>>(wo, p_wT + 3 * DM * DM);

    // 2) Q/K/V projections on tensor cores (half out)
    const int gsmem = 4 * HG_BUF * 2;   // 73728 bytes
    cudaFuncSetAttribute(hgemm_kernel<true>,
                         cudaFuncAttributeMaxDynamicSharedMemorySize, gsmem);
    cudaFuncSetAttribute(hgemm_kernel<false>,
                         cudaFuncAttributeMaxDynamicSharedMemorySize, gsmem);
    dim3 gg(DM / 128, NTOK / 128);      // (8, 64)
    hgemm_kernel<true><<<gg, 256, gsmem>>>(p_xh, p_wT + 0 * DM * DM, bq, nullptr, p_qh);
    hgemm_kernel<true><<<gg, 256, gsmem>>>(p_xh, p_wT + 1 * DM * DM, bk, nullptr, p_kh);
    hgemm_kernel<true><<<gg, 256, gsmem>>>(p_xh, p_wT + 2 * DM * DM, bv, nullptr, p_vh);

    // 2b) V -> [b][h][d][s]
    v_transpose_kernel<<<dim3(SQ / 32, HD / 32, BB * HH), tb>>>();

    // 3) attention
    cudaFuncSetAttribute(flash_kernel,
                         cudaFuncAttributeMaxDynamicSharedMemorySize, F_SMEM);
    flash_kernel<<<dim3(SQ / 128, HH, BB), 256, F_SMEM>>>();

    // 4) output projection + bias + residual -> d_out (fp32)
    hgemm_kernel<false><<<gg, 256, gsmem>>>(p_ah, p_wT + 3 * DM * DM, bo, p_xpe, out);

    // 5) in-place layernorm
    layernorm_kernel<<<NTOK, 256>>>(out, gamma, beta);
}

// round 13
// speedup vs baseline: 7.7560x; 1.0330x over previous
#include <cuda_runtime.h>
#include <cuda_fp16.h>
#include <math.h>
#include <stdint.h>

// Problem constants (fixed by the reference)
#define DM   1024
#define SQ   2048
#define BB   4
#define HH   16
#define HD   64
#define NTOK (BB * SQ)   // 8192

// ---------------------------------------------------------------------------
// Scratch (device globals; no dynamic allocation allowed)
// ---------------------------------------------------------------------------
__device__ float  g_xpe[NTOK * DM];      // x + pe, fp32 (residual)
__device__ __half g_xh [NTOK * DM];      // x + pe, fp16 (GEMM A)
__device__ __half g_wTh[4 * DM * DM];    // transposed fp16 weights [N][K]
__device__ __half g_qh [NTOK * DM];
__device__ __half g_kh [NTOK * DM];
__device__ __half g_vh [NTOK * DM];
__device__ __half g_vt [NTOK * DM];      // V transposed: [b][h][d][s]
__device__ __half g_ah [NTOK * DM];      // attention out, fp16

// ---------------------------------------------------------------------------
// helpers
// ---------------------------------------------------------------------------
__device__ __forceinline__ uint32_t smem_u32(const void* p) {
    uint32_t a;
    asm("{ .reg .u64 t; cvta.to.shared.u64 t, %1; cvt.u32.u64 %0, t; }" : "=r"(a) : "l"(p));
    return a;
}

#define CP_ASYNC16(saddr, gptr) \
    asm volatile("cp.async.cg.shared.global [%0], [%1], 16;" :: "r"(saddr), "l"(gptr))
#define CP_COMMIT() asm volatile("cp.async.commit_group;" ::: "memory")
#define CP_WAIT1()  asm volatile("cp.async.wait_group 1;" ::: "memory")
#define CP_WAIT0()  asm volatile("cp.async.wait_group 0;" ::: "memory")

#define LDSM_X4(r0, r1, r2, r3, addr) \
    asm volatile("ldmatrix.sync.aligned.m8n8.x4.shared.b16 {%0,%1,%2,%3}, [%4];" \
                 : "=r"(r0), "=r"(r1), "=r"(r2), "=r"(r3) : "r"(addr))
#define LDSM_X2(r0, r1, addr) \
    asm volatile("ldmatrix.sync.aligned.m8n8.x2.shared.b16 {%0,%1}, [%2];" \
                 : "=r"(r0), "=r"(r1) : "r"(addr))

// D(f32x4) += A(f16 m16k16) * B(f16 k16n8)
__device__ __forceinline__ void mma_f16(float& d0, float& d1, float& d2, float& d3,
    uint32_t a0, uint32_t a1, uint32_t a2, uint32_t a3, uint32_t b0, uint32_t b1)
{
    asm volatile("mma.sync.aligned.m16n8k16.row.col.f32.f16.f16.f32 "
        "{%0,%1,%2,%3}, {%4,%5,%6,%7}, {%8,%9}, {%0,%1,%2,%3};"
        : "+f"(d0), "+f"(d1), "+f"(d2), "+f"(d3)
        : "r"(a0), "r"(a1), "r"(a2), "r"(a3), "r"(b0), "r"(b1));
}

// ---------------------------------------------------------------------------
// 1) x + pe -> fp32 copy (residual) + fp16 copy (GEMM A)
// ---------------------------------------------------------------------------
__global__ __launch_bounds__(256) void add_pe_kernel(const float* __restrict__ x,
                                                     const float* __restrict__ pe) {
    int i = blockIdx.x * blockDim.x + threadIdx.x;  // float4 index
    float4 xv = reinterpret_cast<const float4*>(x)[i];
    int d4  = i & (DM / 4 - 1);
    int tok = i >> 8;
    int s   = tok & (SQ - 1);
    float4 pv = reinterpret_cast<const float4*>(pe)[s * (DM / 4) + d4];
    xv.x += pv.x; xv.y += pv.y; xv.z += pv.z; xv.w += pv.w;
    reinterpret_cast<float4*>(g_xpe)[i] = xv;
    __half2 h0 = __floats2half2_rn(xv.x, xv.y);
    __half2 h1 = __floats2half2_rn(xv.z, xv.w);
    reinterpret_cast<__half2*>(g_xh)[i * 2 + 0] = h0;
    reinterpret_cast<__half2*>(g_xh)[i * 2 + 1] = h1;
}

// ---------------------------------------------------------------------------
// 1b) all 4 weight transposes in one launch: WT[z][n][k] = half(Wz[k][n])
// ---------------------------------------------------------------------------
__global__ __launch_bounds__(256) void transpose_w_kernel(
    const float* __restrict__ w0, const float* __restrict__ w1,
    const float* __restrict__ w2, const float* __restrict__ w3) {
    __shared__ float t[32][33];
    const float* W = (blockIdx.z == 0) ? w0 : (blockIdx.z == 1) ? w1
                   : (blockIdx.z == 2) ? w2 : w3;
    __half* WT = g_wTh + (size_t)blockIdx.z * DM * DM;
    int tx = threadIdx.x, ty = threadIdx.y;       // 32 x 8
    int x = blockIdx.x * 32 + tx;                 // n
    int y = blockIdx.y * 32 + ty;                 // k
#pragma unroll
    for (int i = 0; i < 32; i += 8)
        t[ty + i][tx] = W[(size_t)(y + i) * DM + x];
    __syncthreads();
    int x2 = blockIdx.y * 32 + tx;                // k
    int y2 = blockIdx.x * 32 + ty;                // n
#pragma unroll
    for (int i = 0; i < 32; i += 8)
        WT[(size_t)(y2 + i) * DM + x2] = __float2half(t[tx][ty + i]);
}

// ---------------------------------------------------------------------------
// 1c) V transpose: g_vh [tok][DM] -> g_vt [b][h][d][s]  (half)
// ---------------------------------------------------------------------------
__global__ __launch_bounds__(256) void v_transpose_kernel() {
    __shared__ __half t[32][33];
    int tx = threadIdx.x, ty = threadIdx.y;       // 32 x 8
    int z = blockIdx.z;                           // b*16 + h
    int b = z >> 4, h = z & 15;
    int s0 = blockIdx.x * 32, d0 = blockIdx.y * 32;
#pragma unroll
    for (int i = 0; i < 32; i += 8)
        t[ty + i][tx] = g_vh[((size_t)(b * SQ + s0 + ty + i)) * DM + h * HD + d0 + tx];
    __syncthreads();
#pragma unroll
    for (int i = 0; i < 32; i += 8)
        g_vt[((size_t)z * HD + d0 + ty + i) * SQ + s0 + tx] = t[tx][ty + i];
}

// ---------------------------------------------------------------------------
// 2) fp16 tensor-core GEMM, 128x128 CTA tile, 8 warps of 64x32, BK=64,
//    cp.async double buffer, ldmatrix fragment loads.
//    QKV mode: blockIdx.x in [0,24): mat = x>>3 selects (WT,bias,out), half out.
//    O mode:   single matrix, fp32 out = acc + bias + residual.
// ---------------------------------------------------------------------------
#define HG_STRIDE 72                      // halfs per smem row
#define HG_BUF    (128 * HG_STRIDE)      // halfs per matrix buffer

template <bool QKV>
__global__ __launch_bounds__(256) void hgemm_kernel(
    const __half* __restrict__ A, const __half* __restrict__ WT,
    const float* __restrict__ b0, const float* __restrict__ b1,
    const float* __restrict__ b2, const float* __restrict__ R,
    void* o0, void* o1, void* o2)
{
    extern __shared__ __half hsm[];
    __half* As = hsm;                     // [2][128][72]
    __half* Bs = hsm + 2 * HG_BUF;        // [2][128][72]

    const int tid = threadIdx.x;
    const int wid = tid >> 5, lane = tid & 31;
    const int r = lane >> 2, cq = lane & 3;
    const int wm = (wid >> 2) * 64;       // warp m offset
    const int wn = (wid & 3) * 32;        // warp n offset
    const int m0 = blockIdx.y * 128;

    int mat, n0;
    if (QKV) { mat = blockIdx.x >> 3; n0 = (blockIdx.x & 7) * 128; }
    else     { mat = 0;               n0 = blockIdx.x * 128; }
    const __half* BT = WT + (QKV ? (size_t)mat * DM * DM : 0);
    const float* bias = QKV ? (mat == 0 ? b0 : (mat == 1 ? b1 : b2)) : b0;
    void* Cout = QKV ? (mat == 0 ? o0 : (mat == 1 ? o1 : o2)) : o0;

    // cp.async geometry: tile 128 rows x 64 halfs = 8 chunks/row; 4 chunks/thread
    const __half* ag[4]; const __half* bg[4]; uint32_t so[4];
#pragma unroll
    for (int i = 0; i < 4; ++i) {
        int idx = i * 256 + tid;
        int row = idx >> 3, c8 = idx & 7;
        ag[i] = A  + (size_t)(m0 + row) * DM + c8 * 8;
        bg[i] = BT + (size_t)(n0 + row) * DM + c8 * 8;
        so[i] = (uint32_t)(row * HG_STRIDE + c8 * 8) * 2;   // bytes
    }
    const uint32_t As_u = smem_u32(As), Bs_u = smem_u32(Bs);

    // ldmatrix lane addressing (bytes, sans buffer/kt offset)
    const int aRow = lane & 15, aC8 = (lane >> 4) * 8;
    const int bIdx = lane & 15, bRow = bIdx & 7, bC8 = (bIdx >> 3) * 8;
    uint32_t aOff[4], bOff[4];
#pragma unroll
    for (int mt = 0; mt < 4; ++mt)
        aOff[mt] = (uint32_t)((wm + mt * 16 + aRow) * HG_STRIDE + aC8) * 2;
#pragma unroll
    for (int nt = 0; nt < 4; ++nt)
        bOff[nt] = (uint32_t)((wn + nt * 8 + bRow) * HG_STRIDE + bC8) * 2;

    float acc[16][4] = {};   // [mt*4+nt]

    // prologue: buffer 0, k=0
#pragma unroll
    for (int i = 0; i < 4; ++i) {
        CP_ASYNC16(As_u + so[i], ag[i]);
        CP_ASYNC16(Bs_u + so[i], bg[i]);
    }
    CP_COMMIT();

    for (int s = 0; s < 16; ++s) {        // K = 1024, BK = 64
        const int buf = s & 1;
        if (s + 1 < 16) {
            const int ob = buf ^ 1;
            const int koff = (s + 1) * 64;
#pragma unroll
            for (int i = 0; i < 4; ++i) {
                CP_ASYNC16(As_u + (uint32_t)(ob * HG_BUF * 2) + so[i], ag[i] + koff);
                CP_ASYNC16(Bs_u + (uint32_t)(ob * HG_BUF * 2) + so[i], bg[i] + koff);
            }
            CP_COMMIT();
            CP_WAIT1();
        } else {
            CP_WAIT0();
        }
        __syncthreads();

        const uint32_t Ab = As_u + (uint32_t)(buf * HG_BUF * 2);
        const uint32_t Bb = Bs_u + (uint32_t)(buf * HG_BUF * 2);

#pragma unroll
        for (int kt = 0; kt < 4; ++kt) {          // 4 x k16
            const uint32_t ko = kt * 32;          // 16 halfs
            uint32_t af[4][4], bf[4][2];
#pragma unroll
            for (int mt = 0; mt < 4; ++mt)
                LDSM_X4(af[mt][0], af[mt][1], af[mt][2], af[mt][3], Ab + aOff[mt] + ko);
#pragma unroll
            for (int nt = 0; nt < 4; ++nt)
                LDSM_X2(bf[nt][0], bf[nt][1], Bb + bOff[nt] + ko);
#pragma unroll
            for (int mt = 0; mt < 4; ++mt)
#pragma unroll
                for (int nt = 0; nt < 4; ++nt)
                    mma_f16(acc[mt * 4 + nt][0], acc[mt * 4 + nt][1],
                            acc[mt * 4 + nt][2], acc[mt * 4 + nt][3],
                            af[mt][0], af[mt][1], af[mt][2], af[mt][3],
                            bf[nt][0], bf[nt][1]);
        }
        __syncthreads();
    }

    // epilogue
#pragma unroll
    for (int mt = 0; mt < 4; ++mt) {
        const int row0 = m0 + wm + mt * 16 + r;
#pragma unroll
        for (int nt = 0; nt < 4; ++nt) {
            const int col = n0 + wn + nt * 8 + cq * 2;
            float2 bv = *reinterpret_cast<const float2*>(&bias[col]);
            float* a4 = acc[mt * 4 + nt];
            float v00 = a4[0] + bv.x, v01 = a4[1] + bv.y;
            float v10 = a4[2] + bv.x, v11 = a4[3] + bv.y;
            if (QKV) {
                __half* C = (__half*)Cout;
                *reinterpret_cast<__half2*>(&C[(size_t)row0 * DM + col]) =
                    __floats2half2_rn(v00, v01);
                *reinterpret_cast<__half2*>(&C[(size_t)(row0 + 8) * DM + col]) =
                    __floats2half2_rn(v10, v11);
            } else {
                float* C = (float*)Cout;
                float2 r0v = *reinterpret_cast<const float2*>(&R[(size_t)row0 * DM + col]);
                float2 r1v = *reinterpret_cast<const float2*>(&R[(size_t)(row0 + 8) * DM + col]);
                *reinterpret_cast<float2*>(&C[(size_t)row0 * DM + col]) =
                    make_float2(v00 + r0v.x, v01 + r0v.y);
                *reinterpret_cast<float2*>(&C[(size_t)(row0 + 8) * DM + col]) =
                    make_float2(v10 + r1v.x, v11 + r1v.y);
            }
        }
    }
}

// ---------------------------------------------------------------------------
// 3) Flash attention, fp16 mma + h2exp2 softmax, ldmatrix frag loads.
//    Block: 256 thr (8 warps x 16 q-rows = 128 q-rows), K-tiles of 64.
//    Softmax denominator: direct fp32 sum of register-resident half P.
// ---------------------------------------------------------------------------
#define FQ_H   (128 * 72)   // Q halfs
#define FK_H   (64 * 72)    // K halfs per buffer
#define FV_H   (64 * 72)    // Vt halfs per buffer
#define F_SMEM ((FQ_H + 2 * FK_H + 2 * FV_H) * 2)   // 55296 bytes

__global__ __launch_bounds__(256) void flash_kernel() {
    extern __shared__ __half hsm[];
    __half* Qs  = hsm;                       // [128][72]
    __half* Ksm = hsm + FQ_H;                // [2][64][72]
    __half* Vts = hsm + FQ_H + 2 * FK_H;     // [2][64][72]

    const int qt = blockIdx.x, h = blockIdx.y, b = blockIdx.z;
    const int tid = threadIdx.x, wid = tid >> 5, lane = tid & 31;
    const int r = lane >> 2, cq = lane & 3;
    const int q0 = qt * 128;
    const int bh = b * HH + h;

    const __half* Qg = g_qh + (size_t)b * SQ * DM + h * HD;
    const __half* Kg = g_kh + (size_t)b * SQ * DM + h * HD;
    const __half* Vg = g_vt + (size_t)bh * HD * SQ;      // [d][s]

    // load Q tile [128][64]
    for (int idx = tid; idx < 128 * 8; idx += 256) {     // 16B chunks
        int row = idx >> 3, c8 = idx & 7;
        *reinterpret_cast<uint4*>(&Qs[row * 72 + c8 * 8]) =
            *reinterpret_cast<const uint4*>(&Qg[(size_t)(q0 + row) * DM + c8 * 8]);
    }

    // cp.async geometry for K / Vt tiles: 64 rows x 64 halfs; 2 chunks/thread
    const __half* kg[2]; const __half* vg[2]; uint32_t kvo[2];
#pragma unroll
    for (int i = 0; i < 2; ++i) {
        int idx = i * 256 + tid;
        int row = idx >> 3, c8 = idx & 7;
        kg[i] = Kg + (size_t)row * DM + c8 * 8;   // K rows: seq
        vg[i] = Vg + (size_t)row * SQ + c8 * 8;   // Vt rows: d
        kvo[i] = (uint32_t)(row * 72 + c8 * 8) * 2;
    }
    const uint32_t Ks_u = smem_u32(Ksm), Vt_u = smem_u32(Vts);
    const uint32_t Qs_u = smem_u32(Qs);

    // ldmatrix lane addressing
    const int aRow = lane & 15, aC8 = (lane >> 4) * 8;
    const int bIdx = lane & 15, bRow = bIdx & 7, bC8 = (bIdx >> 3) * 8;
    uint32_t kOff[8];
#pragma unroll
    for (int nt = 0; nt < 8; ++nt)
        kOff[nt] = (uint32_t)((nt * 8 + bRow) * 72 + bC8) * 2;
    // V uses the same per-dt offsets as kOff (same [64][72] geometry)

    __syncthreads();   // Q visible

    // preload Q fragments (4 k16-tiles) via ldmatrix
    uint32_t qa[4][4];
    {
        const uint32_t qbase = Qs_u + (uint32_t)((wid * 16 + aRow) * 72 + aC8) * 2;
#pragma unroll
        for (int kt = 0; kt < 4; ++kt)
            LDSM_X4(qa[kt][0], qa[kt][1], qa[kt][2], qa[kt][3], qbase + kt * 32);
    }

    // prologue: tile 0 into buffer 0
#pragma unroll
    for (int i = 0; i < 2; ++i) {
        CP_ASYNC16(Ks_u + kvo[i], kg[i]);
        CP_ASYNC16(Vt_u + kvo[i], vg[i]);
    }
    CP_COMMIT();

    float o[8][4] = {};
    float l0s = 0.f, l1s = 0.f;
    float m0s = -1e30f, m1s = -1e30f;     // running max (log2-scaled domain)
    const float LC = 0.18033688f;         // 0.125 * log2(e)

    for (int t = 0; t < SQ / 64; ++t) {
        const int buf = t & 1;
        if (t + 1 < SQ / 64) {
            const int ob = buf ^ 1;
#pragma unroll
            for (int i = 0; i < 2; ++i) {
                CP_ASYNC16(Ks_u + (uint32_t)(ob * FK_H * 2) + kvo[i],
                           kg[i] + (size_t)(t + 1) * 64 * DM);
                CP_ASYNC16(Vt_u + (uint32_t)(ob * FV_H * 2) + kvo[i],
                           vg[i] + (t + 1) * 64);
            }
            CP_COMMIT();
            CP_WAIT1();
        } else {
            CP_WAIT0();
        }
        __syncthreads();

        const uint32_t Kb = Ks_u + (uint32_t)(buf * FK_H * 2);
        const uint32_t Vb = Vt_u + (uint32_t)(buf * FV_H * 2);

        // S = Q K^T : 8 n-tiles x 4 k16
        float s[8][4] = {};
#pragma unroll
        for (int nt = 0; nt < 8; ++nt) {
#pragma unroll
            for (int kt = 0; kt < 4; ++kt) {
                uint32_t kf0, kf1;
                LDSM_X2(kf0, kf1, Kb + kOff[nt] + kt * 32);
                mma_f16(s[nt][0], s[nt][1], s[nt][2], s[nt][3],
                        qa[kt][0], qa[kt][1], qa[kt][2], qa[kt][3], kf0, kf1);
            }
        }

        // online softmax (rows r and r+8; reduce over 4 threads sharing each row)
        float rm0 = -1e30f, rm1 = -1e30f;
#pragma unroll
        for (int nt = 0; nt < 8; ++nt) {
            rm0 = fmaxf(rm0, fmaxf(s[nt][0], s[nt][1]));
            rm1 = fmaxf(rm1, fmaxf(s[nt][2], s[nt][3]));
        }
        rm0 = fmaxf(rm0, __shfl_xor_sync(0xffffffffu, rm0, 1));
        rm0 = fmaxf(rm0, __shfl_xor_sync(0xffffffffu, rm0, 2));
        rm1 = fmaxf(rm1, __shfl_xor_sync(0xffffffffu, rm1, 1));
        rm1 = fmaxf(rm1, __shfl_xor_sync(0xffffffffu, rm1, 2));
        const float mn0 = fmaxf(m0s, rm0 * LC);
        const float mn1 = fmaxf(m1s, rm1 * LC);
        const float al0 = exp2f(m0s - mn0);
        const float al1 = exp2f(m1s - mn1);
        m0s = mn0; m1s = mn1;

        // P = exp2(S*LC - m); half2 pairs == fp16 A-fragment registers
        uint32_t ph0[8], ph1[8];
        float rs0 = 0.f, rs1 = 0.f;
#pragma unroll
        for (int nt = 0; nt < 8; ++nt) {
            __half2 e0 = h2exp2(__floats2half2_rn(fmaf(s[nt][0], LC, -mn0),
                                                  fmaf(s[nt][1], LC, -mn0)));
            __half2 e1 = h2exp2(__floats2half2_rn(fmaf(s[nt][2], LC, -mn1),
                                                  fmaf(s[nt][3], LC, -mn1)));
            ph0[nt] = *reinterpret_cast<uint32_t*>(&e0);
            ph1[nt] = *reinterpret_cast<uint32_t*>(&e1);
            float2 f0 = __half22float2(e0);
            float2 f1 = __half22float2(e1);
            rs0 += f0.x + f0.y;
            rs1 += f1.x + f1.y;
        }
        rs0 += __shfl_xor_sync(0xffffffffu, rs0, 1);
        rs0 += __shfl_xor_sync(0xffffffffu, rs0, 2);
        rs1 += __shfl_xor_sync(0xffffffffu, rs1, 1);
        rs1 += __shfl_xor_sync(0xffffffffu, rs1, 2);
        l0s = l0s * al0 + rs0;
        l1s = l1s * al1 + rs1;

        // rescale O by alpha
#pragma unroll
        for (int dt = 0; dt < 8; ++dt) {
            o[dt][0] *= al0; o[dt][1] *= al0;
            o[dt][2] *= al1; o[dt][3] *= al1;
        }

        // O += P @ V
#pragma unroll
        for (int jt = 0; jt < 4; ++jt) {
            uint32_t a0 = ph0[2 * jt], a1 = ph1[2 * jt];
            uint32_t a2 = ph0[2 * jt + 1], a3 = ph1[2 * jt + 1];
#pragma unroll
            for (int dt = 0; dt < 8; ++dt) {
                uint32_t vf0, vf1;
                LDSM_X2(vf0, vf1, Vb + kOff[dt] + jt * 32);
                mma_f16(o[dt][0], o[dt][1], o[dt][2], o[dt][3],
                        a0, a1, a2, a3, vf0, vf1);
            }
        }
        __syncthreads();
    }

    const float inv0 = 1.f / l0s, inv1 = 1.f / l1s;

    __half* Og = g_ah + (size_t)b * SQ * DM + h * HD;
    const int row0 = q0 + wid * 16 + r;
#pragma unroll
    for (int dt = 0; dt < 8; ++dt) {
        const int col = dt * 8 + cq * 2;
        *reinterpret_cast<__half2*>(&Og[(size_t)row0 * DM + col]) =
            __floats2half2_rn(o[dt][0] * inv0, o[dt][1] * inv0);
        *reinterpret_cast<__half2*>(&Og[(size_t)(row0 + 8) * DM + col]) =
            __floats2half2_rn(o[dt][2] * inv1, o[dt][3] * inv1);
    }
}

// ---------------------------------------------------------------------------
// 4) In-place LayerNorm over last dim (1024), one block per row
// ---------------------------------------------------------------------------
__global__ __launch_bounds__(256) void layernorm_kernel(float* __restrict__ out,
                                                        const float* __restrict__ gamma,
                                                        const float* __restrict__ beta) {
    const int row = blockIdx.x, tid = threadIdx.x;
    float4* rowp = reinterpret_cast<float4*>(out) + (size_t)row * 256;
    float4 v = rowp[tid];
    float sum = v.x + v.y + v.z + v.w;
    float sq  = v.x * v.x + v.y * v.y + v.z * v.z + v.w * v.w;
#pragma unroll
    for (int off = 16; off; off >>= 1) {
        sum += __shfl_xor_sync(0xffffffffu, sum, off);
        sq  += __shfl_xor_sync(0xffffffffu, sq, off);
    }
    __shared__ float s1[8], s2[8];
    __shared__ float s_mu, s_inv;
    const int wid = tid >> 5, lane = tid & 31;
    if (lane == 0) { s1[wid] = sum; s2[wid] = sq; }
    __syncthreads();
    if (tid == 0) {
        float ts = 0.f, tq = 0.f;
#pragma unroll
        for (int w = 0; w < 8; ++w) { ts += s1[w]; tq += s2[w]; }
        float mu  = ts * (1.f / 1024.f);
        float var = tq * (1.f / 1024.f) - mu * mu;
        s_mu = mu;
        s_inv = rsqrtf(var + 1e-5f);
    }
    __syncthreads();
    const float mu = s_mu, inv = s_inv;
    float4 g  = reinterpret_cast<const float4*>(gamma)[tid];
    float4 be = reinterpret_cast<const float4*>(beta)[tid];
    v.x = (v.x - mu) * inv * g.x + be.x;
    v.y = (v.y - mu) * inv * g.y + be.y;
    v.z = (v.z - mu) * inv * g.z + be.z;
    v.w = (v.w - mu) * inv * g.w + be.w;
    rowp[tid] = v;
}

// ---------------------------------------------------------------------------
// launch
// ---------------------------------------------------------------------------
extern "C" void kernel_launch(void* const* d_in, const int* in_sizes, int n_in,
                              void* d_out, int out_size) {
    const float* x     = (const float*)d_in[0];
    const float* wq    = (const float*)d_in[1];
    const float* bq    = (const float*)d_in[2];
    const float* wk    = (const float*)d_in[3];
    const float* bk    = (const float*)d_in[4];
    const float* wv    = (const float*)d_in[5];
    const float* bv    = (const float*)d_in[6];
    const float* wo    = (const float*)d_in[7];
    const float* bo    = (const float*)d_in[8];
    const float* gamma = (const float*)d_in[9];
    const float* beta  = (const float*)d_in[10];
    const float* pe    = (const float*)d_in[11];
    float* out = (float*)d_out;

    float *p_xpe;
    __half *p_xh, *p_wT, *p_qh, *p_kh, *p_vh, *p_ah;
    cudaGetSymbolAddress((void**)&p_xpe, g_xpe);
    cudaGetSymbolAddress((void**)&p_xh,  g_xh);
    cudaGetSymbolAddress((void**)&p_wT,  g_wTh);
    cudaGetSymbolAddress((void**)&p_qh,  g_qh);
    cudaGetSymbolAddress((void**)&p_kh,  g_kh);
    cudaGetSymbolAddress((void**)&p_vh,  g_vh);
    cudaGetSymbolAddress((void**)&p_ah,  g_ah);

    // 1) x + pe
    add_pe_kernel<<<NTOK * DM / 4 / 256, 256>>>(x, pe);

    // 1b) transpose + halve all weights (one launch)
    dim3 tb(32, 8);
    transpose_w_kernel<<<dim3(DM / 32, DM / 32, 4), tb>>>(wq, wk, wv, wo);

    // 2) fused Q/K/V projections on tensor cores (half out)
    const int gsmem = 4 * HG_BUF * 2;   // 73728 bytes
    cudaFuncSetAttribute(hgemm_kernel<true>,
                         cudaFuncAttributeMaxDynamicSharedMemorySize, gsmem);
    cudaFuncSetAttribute(hgemm_kernel<false>,
                         cudaFuncAttributeMaxDynamicSharedMemorySize, gsmem);
    hgemm_kernel<true><<<dim3(24, NTOK / 128), 256, gsmem>>>(
        p_xh, p_wT, bq, bk, bv, nullptr, p_qh, p_kh, p_vh);

    // 2b) V -> [b][h][d][s]
    v_transpose_kernel<<<dim3(SQ / 32, HD / 32, BB * HH), tb>>>();

    // 3) attention
    cudaFuncSetAttribute(flash_kernel,
                         cudaFuncAttributeMaxDynamicSharedMemorySize, F_SMEM);
    flash_kernel<<<dim3(SQ / 128, HH, BB), 256, F_SMEM>>>();

    // 4) output projection + bias + residual -> d_out (fp32)
    hgemm_kernel<false><<<dim3(8, NTOK / 128), 256, gsmem>>>(
        p_ah, p_wT + 3 * (size_t)DM * DM, bo, nullptr, nullptr, p_xpe, out, nullptr, nullptr);

    // 5) in-place layernorm
    layernorm_kernel<<<NTOK, 256>>>(out, gamma, beta);
}

// round 15
// speedup vs baseline: 8.0087x; 1.0326x over previous
#include <cuda_runtime.h>
#include <cuda_fp16.h>
#include <math.h>
#include <stdint.h>

// Problem constants (fixed by the reference)
#define DM   1024
#define SQ   2048
#define BB   4
#define HH   16
#define HD   64
#define NTOK (BB * SQ)   // 8192

// ---------------------------------------------------------------------------
// Scratch (device globals; no dynamic allocation allowed)
// ---------------------------------------------------------------------------
__device__ float  g_xpe[NTOK * DM];      // x + pe, fp32 (residual)
__device__ __half g_xh [NTOK * DM];      // x + pe, fp16 (GEMM A)
__device__ __half g_wTh[4 * DM * DM];    // transposed fp16 weights [N][K]
__device__ __half g_qh [NTOK * DM];
__device__ __half g_kh [NTOK * DM];
__device__ __half g_vh [NTOK * DM];
__device__ __half g_ah [NTOK * DM];      // attention out, fp16

// ---------------------------------------------------------------------------
// helpers
// ---------------------------------------------------------------------------
__device__ __forceinline__ uint32_t smem_u32(const void* p) {
    uint32_t a;
    asm("{ .reg .u64 t; cvta.to.shared.u64 t, %1; cvt.u32.u64 %0, t; }" : "=r"(a) : "l"(p));
    return a;
}

#define CP_ASYNC16(saddr, gptr) \
    asm volatile("cp.async.cg.shared.global [%0], [%1], 16;" :: "r"(saddr), "l"(gptr))
#define CP_COMMIT() asm volatile("cp.async.commit_group;" ::: "memory")
#define CP_WAIT1()  asm volatile("cp.async.wait_group 1;" ::: "memory")
#define CP_WAIT0()  asm volatile("cp.async.wait_group 0;" ::: "memory")

#define LDSM_X4(r0, r1, r2, r3, addr) \
    asm volatile("ldmatrix.sync.aligned.m8n8.x4.shared.b16 {%0,%1,%2,%3}, [%4];" \
                 : "=r"(r0), "=r"(r1), "=r"(r2), "=r"(r3) : "r"(addr))
#define LDSM_X2(r0, r1, addr) \
    asm volatile("ldmatrix.sync.aligned.m8n8.x2.shared.b16 {%0,%1}, [%2];" \
                 : "=r"(r0), "=r"(r1) : "r"(addr))
#define LDSM_X2_TRANS(r0, r1, addr) \
    asm volatile("ldmatrix.sync.aligned.m8n8.x2.trans.shared.b16 {%0,%1}, [%2];" \
                 : "=r"(r0), "=r"(r1) : "r"(addr))

// D(f32x4) += A(f16 m16k16) * B(f16 k16n8)
__device__ __forceinline__ void mma_f16(float& d0, float& d1, float& d2, float& d3,
    uint32_t a0, uint32_t a1, uint32_t a2, uint32_t a3, uint32_t b0, uint32_t b1)
{
    asm volatile("mma.sync.aligned.m16n8k16.row.col.f32.f16.f16.f32 "
        "{%0,%1,%2,%3}, {%4,%5,%6,%7}, {%8,%9}, {%0,%1,%2,%3};"
        : "+f"(d0), "+f"(d1), "+f"(d2), "+f"(d3)
        : "r"(a0), "r"(a1), "r"(a2), "r"(a3), "r"(b0), "r"(b1));
}

// ---------------------------------------------------------------------------
// 1) x + pe -> fp32 copy (residual) + fp16 copy (GEMM A)
// ---------------------------------------------------------------------------
__global__ __launch_bounds__(256) void add_pe_kernel(const float* __restrict__ x,
                                                     const float* __restrict__ pe) {
    int i = blockIdx.x * blockDim.x + threadIdx.x;  // float4 index
    float4 xv = reinterpret_cast<const float4*>(x)[i];
    int d4  = i & (DM / 4 - 1);
    int tok = i >> 8;
    int s   = tok & (SQ - 1);
    float4 pv = reinterpret_cast<const float4*>(pe)[s * (DM / 4) + d4];
    xv.x += pv.x; xv.y += pv.y; xv.z += pv.z; xv.w += pv.w;
    reinterpret_cast<float4*>(g_xpe)[i] = xv;
    __half2 h0 = __floats2half2_rn(xv.x, xv.y);
    __half2 h1 = __floats2half2_rn(xv.z, xv.w);
    reinterpret_cast<__half2*>(g_xh)[i * 2 + 0] = h0;
    reinterpret_cast<__half2*>(g_xh)[i * 2 + 1] = h1;
}

// ---------------------------------------------------------------------------
// 1b) all 4 weight transposes in one launch: WT[z][n][k] = half(Wz[k][n])
// ---------------------------------------------------------------------------
__global__ __launch_bounds__(256) void transpose_w_kernel(
    const float* __restrict__ w0, const float* __restrict__ w1,
    const float* __restrict__ w2, const float* __restrict__ w3) {
    __shared__ float t[32][33];
    const float* W = (blockIdx.z == 0) ? w0 : (blockIdx.z == 1) ? w1
                   : (blockIdx.z == 2) ? w2 : w3;
    __half* WT = g_wTh + (size_t)blockIdx.z * DM * DM;
    int tx = threadIdx.x, ty = threadIdx.y;       // 32 x 8
    int x = blockIdx.x * 32 + tx;                 // n
    int y = blockIdx.y * 32 + ty;                 // k
#pragma unroll
    for (int i = 0; i < 32; i += 8)
        t[ty + i][tx] = W[(size_t)(y + i) * DM + x];
    __syncthreads();
    int x2 = blockIdx.y * 32 + tx;                // k
    int y2 = blockIdx.x * 32 + ty;                // n
#pragma unroll
    for (int i = 0; i < 32; i += 8)
        WT[(size_t)(y2 + i) * DM + x2] = __float2half(t[tx][ty + i]);
}

// ---------------------------------------------------------------------------
// 2) fp16 tensor-core GEMM, 128x128 CTA tile, 8 warps of 64x32, BK=64,
//    cp.async double buffer, ldmatrix fragment loads.
//    QKV mode: blockIdx.x in [0,24): mat = x>>3 selects (WT,bias,out), half out.
//    O mode:   single matrix, fp32 out = acc + bias + residual.
// ---------------------------------------------------------------------------
#define HG_STRIDE 72                      // halfs per smem row
#define HG_BUF    (128 * HG_STRIDE)      // halfs per matrix buffer

template <bool QKV>
__global__ __launch_bounds__(256) void hgemm_kernel(
    const __half* __restrict__ A, const __half* __restrict__ WT,
    const float* __restrict__ b0, const float* __restrict__ b1,
    const float* __restrict__ b2, const float* __restrict__ R,
    void* o0, void* o1, void* o2)
{
    extern __shared__ __half hsm[];
    __half* As = hsm;                     // [2][128][72]
    __half* Bs = hsm + 2 * HG_BUF;        // [2][128][72]

    const int tid = threadIdx.x;
    const int wid = tid >> 5, lane = tid & 31;
    const int r = lane >> 2, cq = lane & 3;
    const int wm = (wid >> 2) * 64;       // warp m offset
    const int wn = (wid & 3) * 32;        // warp n offset
    const int m0 = blockIdx.y * 128;

    int mat, n0;
    if (QKV) { mat = blockIdx.x >> 3; n0 = (blockIdx.x & 7) * 128; }
    else     { mat = 0;               n0 = blockIdx.x * 128; }
    const __half* BT = WT + (QKV ? (size_t)mat * DM * DM : 0);
    const float* bias = QKV ? (mat == 0 ? b0 : (mat == 1 ? b1 : b2)) : b0;
    void* Cout = QKV ? (mat == 0 ? o0 : (mat == 1 ? o1 : o2)) : o0;

    // cp.async geometry: tile 128 rows x 64 halfs = 8 chunks/row; 4 chunks/thread
    const __half* ag[4]; const __half* bg[4]; uint32_t so[4];
#pragma unroll
    for (int i = 0; i < 4; ++i) {
        int idx = i * 256 + tid;
        int row = idx >> 3, c8 = idx & 7;
        ag[i] = A  + (size_t)(m0 + row) * DM + c8 * 8;
        bg[i] = BT + (size_t)(n0 + row) * DM + c8 * 8;
        so[i] = (uint32_t)(row * HG_STRIDE + c8 * 8) * 2;   // bytes
    }
    const uint32_t As_u = smem_u32(As), Bs_u = smem_u32(Bs);

    // ldmatrix lane addressing (bytes, sans buffer/kt offset)
    const int aRow = lane & 15, aC8 = (lane >> 4) * 8;
    const int bIdx = lane & 15, bRow = bIdx & 7, bC8 = (bIdx >> 3) * 8;
    uint32_t aOff[4], bOff[4];
#pragma unroll
    for (int mt = 0; mt < 4; ++mt)
        aOff[mt] = (uint32_t)((wm + mt * 16 + aRow) * HG_STRIDE + aC8) * 2;
#pragma unroll
    for (int nt = 0; nt < 4; ++nt)
        bOff[nt] = (uint32_t)((wn + nt * 8 + bRow) * HG_STRIDE + bC8) * 2;

    float acc[16][4] = {};   // [mt*4+nt]

    // prologue: buffer 0, k=0
#pragma unroll
    for (int i = 0; i < 4; ++i) {
        CP_ASYNC16(As_u + so[i], ag[i]);
        CP_ASYNC16(Bs_u + so[i], bg[i]);
    }
    CP_COMMIT();

    for (int s = 0; s < 16; ++s) {        // K = 1024, BK = 64
        const int buf = s & 1;
        if (s + 1 < 16) {
            const int ob = buf ^ 1;
            const int koff = (s + 1) * 64;
#pragma unroll
            for (int i = 0; i < 4; ++i) {
                CP_ASYNC16(As_u + (uint32_t)(ob * HG_BUF * 2) + so[i], ag[i] + koff);
                CP_ASYNC16(Bs_u + (uint32_t)(ob * HG_BUF * 2) + so[i], bg[i] + koff);
            }
            CP_COMMIT();
            CP_WAIT1();
        } else {
            CP_WAIT0();
        }
        __syncthreads();

        const uint32_t Ab = As_u + (uint32_t)(buf * HG_BUF * 2);
        const uint32_t Bb = Bs_u + (uint32_t)(buf * HG_BUF * 2);

#pragma unroll
        for (int kt = 0; kt < 4; ++kt) {          // 4 x k16
            const uint32_t ko = kt * 32;          // 16 halfs
            uint32_t af[4][4], bf[4][2];
#pragma unroll
            for (int mt = 0; mt < 4; ++mt)
                LDSM_X4(af[mt][0], af[mt][1], af[mt][2], af[mt][3], Ab + aOff[mt] + ko);
#pragma unroll
            for (int nt = 0; nt < 4; ++nt)
                LDSM_X2(bf[nt][0], bf[nt][1], Bb + bOff[nt] + ko);
#pragma unroll
            for (int mt = 0; mt < 4; ++mt)
#pragma unroll
                for (int nt = 0; nt < 4; ++nt)
                    mma_f16(acc[mt * 4 + nt][0], acc[mt * 4 + nt][1],
                            acc[mt * 4 + nt][2], acc[mt * 4 + nt][3],
                            af[mt][0], af[mt][1], af[mt][2], af[mt][3],
                            bf[nt][0], bf[nt][1]);
        }
        __syncthreads();
    }

    // epilogue
#pragma unroll
    for (int mt = 0; mt < 4; ++mt) {
        const int row0 = m0 + wm + mt * 16 + r;
#pragma unroll
        for (int nt = 0; nt < 4; ++nt) {
            const int col = n0 + wn + nt * 8 + cq * 2;
            float2 bv = *reinterpret_cast<const float2*>(&bias[col]);
            float* a4 = acc[mt * 4 + nt];
            float v00 = a4[0] + bv.x, v01 = a4[1] + bv.y;
            float v10 = a4[2] + bv.x, v11 = a4[3] + bv.y;
            if (QKV) {
                __half* C = (__half*)Cout;
                *reinterpret_cast<__half2*>(&C[(size_t)row0 * DM + col]) =
                    __floats2half2_rn(v00, v01);
                *reinterpret_cast<__half2*>(&C[(size_t)(row0 + 8) * DM + col]) =
                    __floats2half2_rn(v10, v11);
            } else {
                float* C = (float*)Cout;
                float2 r0v = *reinterpret_cast<const float2*>(&R[(size_t)row0 * DM + col]);
                float2 r1v = *reinterpret_cast<const float2*>(&R[(size_t)(row0 + 8) * DM + col]);
                *reinterpret_cast<float2*>(&C[(size_t)row0 * DM + col]) =
                    make_float2(v00 + r0v.x, v01 + r0v.y);
                *reinterpret_cast<float2*>(&C[(size_t)(row0 + 8) * DM + col]) =
                    make_float2(v10 + r1v.x, v11 + r1v.y);
            }
        }
    }
}

// ---------------------------------------------------------------------------
// 3) Flash attention, fp16 mma + h2exp2 softmax, ldmatrix frag loads.
//    Block: 256 thr (8 warps x 16 q-rows = 128 q-rows), K-tiles of 64.
//    K and V both stored [s][d] in smem; V fragments via ldmatrix.trans
//    (transposed 8x8 loads give the Vt[d][s] B-fragments directly).
// ---------------------------------------------------------------------------
#define FQ_H   (128 * 72)   // Q halfs
#define FK_H   (64 * 72)    // K halfs per buffer
#define FV_H   (64 * 72)    // V halfs per buffer
#define F_SMEM ((FQ_H + 2 * FK_H + 2 * FV_H) * 2)   // 55296 bytes

__global__ __launch_bounds__(256) void flash_kernel() {
    extern __shared__ __half hsm[];
    __half* Qs  = hsm;                       // [128][72]
    __half* Ksm = hsm + FQ_H;                // [2][64][72]
    __half* Vsm = hsm + FQ_H + 2 * FK_H;     // [2][64][72]  ([s][d])

    const int qt = blockIdx.x, h = blockIdx.y, b = blockIdx.z;
    const int tid = threadIdx.x, wid = tid >> 5, lane = tid & 31;
    const int r = lane >> 2, cq = lane & 3;
    const int q0 = qt * 128;

    const __half* Qg = g_qh + (size_t)b * SQ * DM + h * HD;
    const __half* Kg = g_kh + (size_t)b * SQ * DM + h * HD;
    const __half* Vg = g_vh + (size_t)b * SQ * DM + h * HD;

    // load Q tile [128][64]
    for (int idx = tid; idx < 128 * 8; idx += 256) {     // 16B chunks
        int row = idx >> 3, c8 = idx & 7;
        *reinterpret_cast<uint4*>(&Qs[row * 72 + c8 * 8]) =
            *reinterpret_cast<const uint4*>(&Qg[(size_t)(q0 + row) * DM + c8 * 8]);
    }

    // cp.async geometry for K / V tiles: 64 rows x 64 halfs; 2 chunks/thread
    const __half* kg[2]; const __half* vg[2]; uint32_t kvo[2];
#pragma unroll
    for (int i = 0; i < 2; ++i) {
        int idx = i * 256 + tid;
        int row = idx >> 3, c8 = idx & 7;
        kg[i] = Kg + (size_t)row * DM + c8 * 8;   // K rows: seq
        vg[i] = Vg + (size_t)row * DM + c8 * 8;   // V rows: seq (same layout)
        kvo[i] = (uint32_t)(row * 72 + c8 * 8) * 2;
    }
    const uint32_t Ks_u = smem_u32(Ksm), Vs_u = smem_u32(Vsm);
    const uint32_t Qs_u = smem_u32(Qs);

    // ldmatrix lane addressing
    const int aRow = lane & 15, aC8 = (lane >> 4) * 8;
    const int bIdx = lane & 15, bRow = bIdx & 7, bC8 = (bIdx >> 3) * 8;
    uint32_t kOff[8];
#pragma unroll
    for (int nt = 0; nt < 8; ++nt)
        kOff[nt] = (uint32_t)((nt * 8 + bRow) * 72 + bC8) * 2;
    // V trans-load addressing: lane 0..15 -> s-row (jt*16 + bIdx), col d (dt*8)
    const uint32_t vtBase = (uint32_t)(bIdx * 72) * 2;

    __syncthreads();   // Q visible

    // preload Q fragments (4 k16-tiles) via ldmatrix
    uint32_t qa[4][4];
    {
        const uint32_t qbase = Qs_u + (uint32_t)((wid * 16 + aRow) * 72 + aC8) * 2;
#pragma unroll
        for (int kt = 0; kt < 4; ++kt)
            LDSM_X4(qa[kt][0], qa[kt][1], qa[kt][2], qa[kt][3], qbase + kt * 32);
    }

    // prologue: tile 0 into buffer 0
#pragma unroll
    for (int i = 0; i < 2; ++i) {
        CP_ASYNC16(Ks_u + kvo[i], kg[i]);
        CP_ASYNC16(Vs_u + kvo[i], vg[i]);
    }
    CP_COMMIT();

    float o[8][4] = {};
    float l0s = 0.f, l1s = 0.f;
    float m0s = -1e30f, m1s = -1e30f;     // running max (log2-scaled domain)
    const float LC = 0.18033688f;         // 0.125 * log2(e)

    for (int t = 0; t < SQ / 64; ++t) {
        const int buf = t & 1;
        if (t + 1 < SQ / 64) {
            const int ob = buf ^ 1;
            const size_t adv = (size_t)(t + 1) * 64 * DM;
#pragma unroll
            for (int i = 0; i < 2; ++i) {
                CP_ASYNC16(Ks_u + (uint32_t)(ob * FK_H * 2) + kvo[i], kg[i] + adv);
                CP_ASYNC16(Vs_u + (uint32_t)(ob * FV_H * 2) + kvo[i], vg[i] + adv);
            }
            CP_COMMIT();
            CP_WAIT1();
        } else {
            CP_WAIT0();
        }
        __syncthreads();

        const uint32_t Kb = Ks_u + (uint32_t)(buf * FK_H * 2);
        const uint32_t Vb = Vs_u + (uint32_t)(buf * FV_H * 2);

        // S = Q K^T : 8 n-tiles x 4 k16
        float s[8][4] = {};
#pragma unroll
        for (int nt = 0; nt < 8; ++nt) {
#pragma unroll
            for (int kt = 0; kt < 4; ++kt) {
                uint32_t kf0, kf1;
                LDSM_X2(kf0, kf1, Kb + kOff[nt] + kt * 32);
                mma_f16(s[nt][0], s[nt][1], s[nt][2], s[nt][3],
                        qa[kt][0], qa[kt][1], qa[kt][2], qa[kt][3], kf0, kf1);
            }
        }

        // online softmax (rows r and r+8; reduce over 4 threads sharing each row)
        float rm0 = -1e30f, rm1 = -1e30f;
#pragma unroll
        for (int nt = 0; nt < 8; ++nt) {
            rm0 = fmaxf(rm0, fmaxf(s[nt][0], s[nt][1]));
            rm1 = fmaxf(rm1, fmaxf(s[nt][2], s[nt][3]));
        }
        rm0 = fmaxf(rm0, __shfl_xor_sync(0xffffffffu, rm0, 1));
        rm0 = fmaxf(rm0, __shfl_xor_sync(0xffffffffu, rm0, 2));
        rm1 = fmaxf(rm1, __shfl_xor_sync(0xffffffffu, rm1, 1));
        rm1 = fmaxf(rm1, __shfl_xor_sync(0xffffffffu, rm1, 2));
        const float mn0 = fmaxf(m0s, rm0 * LC);
        const float mn1 = fmaxf(m1s, rm1 * LC);
        const float al0 = exp2f(m0s - mn0);
        const float al1 = exp2f(m1s - mn1);
        m0s = mn0; m1s = mn1;

        // P = exp2(S*LC - m); half2 pairs == fp16 A-fragment registers
        uint32_t ph0[8], ph1[8];
        float rs0 = 0.f, rs1 = 0.f;
#pragma unroll
        for (int nt = 0; nt < 8; ++nt) {
            __half2 e0 = h2exp2(__floats2half2_rn(fmaf(s[nt][0], LC, -mn0),
                                                  fmaf(s[nt][1], LC, -mn0)));
            __half2 e1 = h2exp2(__floats2half2_rn(fmaf(s[nt][2], LC, -mn1),
                                                  fmaf(s[nt][3], LC, -mn1)));
            ph0[nt] = *reinterpret_cast<uint32_t*>(&e0);
            ph1[nt] = *reinterpret_cast<uint32_t*>(&e1);
            float2 f0 = __half22float2(e0);
            float2 f1 = __half22float2(e1);
            rs0 += f0.x + f0.y;
            rs1 += f1.x + f1.y;
        }
        rs0 += __shfl_xor_sync(0xffffffffu, rs0, 1);
        rs0 += __shfl_xor_sync(0xffffffffu, rs0, 2);
        rs1 += __shfl_xor_sync(0xffffffffu, rs1, 1);
        rs1 += __shfl_xor_sync(0xffffffffu, rs1, 2);
        l0s = l0s * al0 + rs0;
        l1s = l1s * al1 + rs1;

        // rescale O by alpha
#pragma unroll
        for (int dt = 0; dt < 8; ++dt) {
            o[dt][0] *= al0; o[dt][1] *= al0;
            o[dt][2] *= al1; o[dt][3] *= al1;
        }

        // O += P @ V   (V [s][d]; trans ldmatrix gives Vt fragments)
#pragma unroll
        for (int jt = 0; jt < 4; ++jt) {
            uint32_t a0 = ph0[2 * jt], a1 = ph1[2 * jt];
            uint32_t a2 = ph0[2 * jt + 1], a3 = ph1[2 * jt + 1];
            const uint32_t vjt = Vb + vtBase + (uint32_t)(jt * 16 * 72 * 2);
#pragma unroll
            for (int dt = 0; dt < 8; ++dt) {
                uint32_t vf0, vf1;
                LDSM_X2_TRANS(vf0, vf1, vjt + dt * 16);
                mma_f16(o[dt][0], o[dt][1], o[dt][2], o[dt][3],
                        a0, a1, a2, a3, vf0, vf1);
            }
        }
        __syncthreads();
    }

    const float inv0 = 1.f / l0s, inv1 = 1.f / l1s;

    __half* Og = g_ah + (size_t)b * SQ * DM + h * HD;
    const int row0 = q0 + wid * 16 + r;
#pragma unroll
    for (int dt = 0; dt < 8; ++dt) {
        const int col = dt * 8 + cq * 2;
        *reinterpret_cast<__half2*>(&Og[(size_t)row0 * DM + col]) =
            __floats2half2_rn(o[dt][0] * inv0, o[dt][1] * inv0);
        *reinterpret_cast<__half2*>(&Og[(size_t)(row0 + 8) * DM + col]) =
            __floats2half2_rn(o[dt][2] * inv1, o[dt][3] * inv1);
    }
}

// ---------------------------------------------------------------------------
// 4) In-place LayerNorm over last dim (1024), one block per row
// ---------------------------------------------------------------------------
__global__ __launch_bounds__(256) void layernorm_kernel(float* __restrict__ out,
                                                        const float* __restrict__ gamma,
                                                        const float* __restrict__ beta) {
    const int row = blockIdx.x, tid = threadIdx.x;
    float4* rowp = reinterpret_cast<float4*>(out) + (size_t)row * 256;
    float4 v = rowp[tid];
    float sum = v.x + v.y + v.z + v.w;
    float sq  = v.x * v.x + v.y * v.y + v.z * v.z + v.w * v.w;
#pragma unroll
    for (int off = 16; off; off >>= 1) {
        sum += __shfl_xor_sync(0xffffffffu, sum, off);
        sq  += __shfl_xor_sync(0xffffffffu, sq, off);
    }
    __shared__ float s1[8], s2[8];
    __shared__ float s_mu, s_inv;
    const int wid = tid >> 5, lane = tid & 31;
    if (lane == 0) { s1[wid] = sum; s2[wid] = sq; }
    __syncthreads();
    if (tid == 0) {
        float ts = 0.f, tq = 0.f;
#pragma unroll
        for (int w = 0; w < 8; ++w) { ts += s1[w]; tq += s2[w]; }
        float mu  = ts * (1.f / 1024.f);
        float var = tq * (1.f / 1024.f) - mu * mu;
        s_mu = mu;
        s_inv = rsqrtf(var + 1e-5f);
    }
    __syncthreads();
    const float mu = s_mu, inv = s_inv;
    float4 g  = reinterpret_cast<const float4*>(gamma)[tid];
    float4 be = reinterpret_cast<const float4*>(beta)[tid];
    v.x = (v.x - mu) * inv * g.x + be.x;
    v.y = (v.y - mu) * inv * g.y + be.y;
    v.z = (v.z - mu) * inv * g.z + be.z;
    v.w = (v.w - mu) * inv * g.w + be.w;
    rowp[tid] = v;
}

// ---------------------------------------------------------------------------
// launch
// ---------------------------------------------------------------------------
extern "C" void kernel_launch(void* const* d_in, const int* in_sizes, int n_in,
                              void* d_out, int out_size) {
    const float* x     = (const float*)d_in[0];
    const float* wq    = (const float*)d_in[1];
    const float* bq    = (const float*)d_in[2];
    const float* wk    = (const float*)d_in[3];
    const float* bk    = (const float*)d_in[4];
    const float* wv    = (const float*)d_in[5];
    const float* bv    = (const float*)d_in[6];
    const float* wo    = (const float*)d_in[7];
    const float* bo    = (const float*)d_in[8];
    const float* gamma = (const float*)d_in[9];
    const float* beta  = (const float*)d_in[10];
    const float* pe    = (const float*)d_in[11];
    float* out = (float*)d_out;

    float *p_xpe;
    __half *p_xh, *p_wT, *p_qh, *p_kh, *p_vh, *p_ah;
    cudaGetSymbolAddress((void**)&p_xpe, g_xpe);
    cudaGetSymbolAddress((void**)&p_xh,  g_xh);
    cudaGetSymbolAddress((void**)&p_wT,  g_wTh);
    cudaGetSymbolAddress((void**)&p_qh,  g_qh);
    cudaGetSymbolAddress((void**)&p_kh,  g_kh);
    cudaGetSymbolAddress((void**)&p_vh,  g_vh);
    cudaGetSymbolAddress((void**)&p_ah,  g_ah);

    // 1) x + pe
    add_pe_kernel<<<NTOK * DM / 4 / 256, 256>>>(x, pe);

    // 1b) transpose + halve all weights (one launch)
    dim3 tb(32, 8);
    transpose_w_kernel<<<dim3(DM / 32, DM / 32, 4), tb>>>(wq, wk, wv, wo);

    // 2) fused Q/K/V projections on tensor cores (half out)
    const int gsmem = 4 * HG_BUF * 2;   // 73728 bytes
    cudaFuncSetAttribute(hgemm_kernel<true>,
                         cudaFuncAttributeMaxDynamicSharedMemorySize, gsmem);
    cudaFuncSetAttribute(hgemm_kernel<false>,
                         cudaFuncAttributeMaxDynamicSharedMemorySize, gsmem);
    hgemm_kernel<true><<<dim3(24, NTOK / 128), 256, gsmem>>>(
        p_xh, p_wT, bq, bk, bv, nullptr, p_qh, p_kh, p_vh);

    // 3) attention (no V pre-transpose needed; ldmatrix.trans in-kernel)
    cudaFuncSetAttribute(flash_kernel,
                         cudaFuncAttributeMaxDynamicSharedMemorySize, F_SMEM);
    flash_kernel<<<dim3(SQ / 128, HH, BB), 256, F_SMEM>>>();

    // 4) output projection + bias + residual -> d_out (fp32)
    hgemm_kernel<false><<<dim3(8, NTOK / 128), 256, gsmem>>>(
        p_ah, p_wT + 3 * (size_t)DM * DM, bo, nullptr, nullptr, p_xpe, out, nullptr, nullptr);

    // 5) in-place layernorm
    layernorm_kernel<<<NTOK, 256>>>(out, gamma, beta);
}